// round 14
// baseline (speedup 1.0000x reference)
#include <cuda_runtime.h>
#include <cuda_bf16.h>
#include <cstdint>

#define NN 16500
#define NE 100000
#define KT 3
#define GEN_EPS 1e-7f
#define BN_EPS 1e-5f

// ---------------- scratch ----------------
__device__ int d_cnt[KT][NN];
__device__ int d_off[KT][NN + 1];
__device__ int d_cur[KT][NN];
__device__ int d_eid[KT][NE];
__device__ float d_hh[(size_t)KT * NN * 512];     // GEMM1 out (f32, stride=ch)
__device__ float d_xcur[NN * 256];
__device__ float d_cs[KT * 512], d_css[KT * 512];
__device__ float d_scale[KT * 512], d_shift[KT * 512];
// int8 split-2 quantized operands
__device__ char  d_aggQH[(size_t)KT * NN * 256], d_aggQL[(size_t)KT * NN * 256];
__device__ char  d_hQH[(size_t)KT * NN * 512],  d_hQL[(size_t)KT * NN * 512];
__device__ char  d_waQH[(size_t)KT * 512 * 256], d_waQL[(size_t)KT * 512 * 256];
__device__ char  d_wbQH[(size_t)KT * 256 * 512], d_wbQL[(size_t)KT * 256 * 512];
__device__ float d_sAgg[KT * NN], d_sH[KT * NN];
__device__ float d_sWa[KT * 512], d_sWb[KT * 256];

// ---------------- helpers ----------------
__device__ __forceinline__ float blockMax256(float v) {
    __shared__ float sr[256];
    int t = threadIdx.x;
    sr[t] = v; __syncthreads();
    for (int o = 128; o > 0; o >>= 1) {
        if (t < o) sr[t] = fmaxf(sr[t], sr[t + o]);
        __syncthreads();
    }
    float r = sr[0]; __syncthreads();
    return r;
}
__device__ __forceinline__ void q2(float v, float inv, char& H, char& L) {
    int q = __float2int_rn(v * inv);
    int h = (q + 128) >> 8;
    H = (char)h; L = (char)(q - (h << 8));
}
__device__ __forceinline__ void imma(int* c, const unsigned* a, const unsigned* b) {
    asm volatile(
        "mma.sync.aligned.m16n8k32.row.col.s32.s8.s8.s32 "
        "{%0,%1,%2,%3}, {%4,%5,%6,%7}, {%8,%9}, {%0,%1,%2,%3};"
        : "+r"(c[0]), "+r"(c[1]), "+r"(c[2]), "+r"(c[3])
        : "r"(a[0]), "r"(a[1]), "r"(a[2]), "r"(a[3]), "r"(b[0]), "r"(b[1]));
}

// ---------------- CSR build ----------------
__global__ void k_count(const int* __restrict__ ei) {
    int i = blockIdx.x * blockDim.x + threadIdx.x;
    if (i >= KT * NE) return;
    int k = i / NE, e = i % NE;
    atomicAdd(&d_cnt[k][ei[k * 2 * NE + NE + e]], 1);
}
__global__ void k_scan() {
    __shared__ int sh[1024];
    int k = blockIdx.x, tid = threadIdx.x;
    int carry = 0;
    if (tid == 0) d_off[k][0] = 0;
    for (int base = 0; base < NN; base += 1024) {
        int i = base + tid;
        int v = (i < NN) ? d_cnt[k][i] : 0;
        sh[tid] = v;
        __syncthreads();
        for (int o = 1; o < 1024; o <<= 1) {
            int t = (tid >= o) ? sh[tid - o] : 0;
            __syncthreads();
            sh[tid] += t;
            __syncthreads();
        }
        int inc = sh[tid], tot = sh[1023];
        if (i < NN) {
            d_off[k][i + 1] = carry + inc;
            d_cur[k][i] = carry + inc - v;
        }
        __syncthreads();
        carry += tot;
    }
}
__global__ void k_fill(const int* __restrict__ ei) {
    int i = blockIdx.x * blockDim.x + threadIdx.x;
    if (i < KT * NE) {
        int k = i / NE, e = i % NE;
        int pos = atomicAdd(&d_cur[k][ei[k * 2 * NE + NE + e]], 1);
        d_eid[k][pos] = e;
    }
    if (i < KT * NN) ((int*)d_cnt)[i] = 0;
}

// ---- weight quantization: per-(z,n) column scale; writes [z][n][Kstr] ----
__global__ void k_qw(const float* __restrict__ W, int Kd, int Nd, int wb) {
    int n = blockIdx.x, z = blockIdx.y, tid = threadIdx.x;
    int Kstr = wb ? 512 : 256;
    int Nmax = wb ? 256 : 512;
    char* oH = wb ? d_wbQH : d_waQH;
    char* oL = wb ? d_wbQL : d_waQL;
    float* sOut = wb ? d_sWb : d_sWa;
    float v0 = 0.f, v1 = 0.f, m = 0.f;
    int k0 = tid, k1 = tid + 256;
    if (k0 < Kd) { v0 = W[((size_t)z * Kd + k0) * Nd + n]; m = fabsf(v0); }
    if (k1 < Kd) { v1 = W[((size_t)z * Kd + k1) * Nd + n]; m = fmaxf(m, fabsf(v1)); }
    float M = blockMax256(m);
    float s = (M > 0.f) ? M / 32512.f : 1.f;
    float inv = 1.f / s;
    size_t ob = ((size_t)z * Nmax + n) * Kstr;
    char H = 0, L = 0;
    if (k0 < Kd) q2(v0, inv, H, L);
    if (k0 < Kstr) { oH[ob + k0] = H; oL[ob + k0] = L; }
    H = 0; L = 0;
    if (k1 < Kd) q2(v1, inv, H, L);
    if (k1 < Kstr) { oH[ob + k1] = H; oL[ob + k1] = L; }
    if (tid == 0) sOut[z * Nmax + n] = s;
}

// ---- aggregation (no-max softmax) + fused row quantization ----
__global__ void k_aggr(const float* __restrict__ xin,
                       const int* __restrict__ ei,
                       const float* __restrict__ ea,
                       const float* __restrict__ WeB,
                       const float* __restrict__ beB, int ci) {
    __shared__ int s_src[192];
    __shared__ float s_a[192];
    int n = blockIdx.x, z = blockIdx.y, tid = threadIdx.x;
    if (n == 0) {
        for (int i = tid; i < 512; i += 256) {
            d_cs[z * 512 + i] = 0.f;
            d_css[z * 512 + i] = 0.f;
        }
    }
    int j0 = d_off[z][n];
    int deg = d_off[z][n + 1] - j0;
    int cap = min(deg, 192);
    const int* src = ei + z * 2 * NE;
    const float* eak = ea + z * NE;
    for (int j = tid; j < cap; j += 256) {
        int e = d_eid[z][j0 + j];
        s_src[j] = src[e];
        s_a[j] = eak[e];
    }
    __syncthreads();
    int c = tid;
    float res = 0.f;
    if (c < ci) {
        float we = WeB[z * ci + c], bec = beB[z * ci + c];
        float xn = xin[n * ci + c];
        float u0 = fmaxf(xn + we + bec, 0.f) + GEN_EPS;
        float den = __expf(u0);
        float ws = u0 * den;
#pragma unroll 4
        for (int j = 0; j < cap; j++) {
            float u = fmaxf(xin[s_src[j] * ci + c] + s_a[j] * we + bec, 0.f) + GEN_EPS;
            float e = __expf(u);
            den += e;
            ws = fmaf(u, e, ws);
        }
        for (int jj = cap; jj < deg; jj++) {
            int e0 = d_eid[z][j0 + jj];
            float u = fmaxf(xin[src[e0] * ci + c] + eak[e0] * we + bec, 0.f) + GEN_EPS;
            float e = __expf(u);
            den += e;
            ws = fmaf(u, e, ws);
        }
        res = ws / den + xn;
    }
    float M = blockMax256(c < ci ? fabsf(res) : 0.f);
    float s = (M > 0.f) ? M / 32512.f : 1.f;
    char H = 0, L = 0;
    if (c < ci) q2(res, 1.f / s, H, L);
    size_t ob = ((size_t)z * NN + n) * 256;
    d_aggQH[ob + c] = H;
    d_aggQL[ob + c] = L;
    if (tid == 0) d_sAgg[z * NN + n] = s;
}

// ---- GEMM core pieces ----
#define ABUF 10240
#define BBUF 5120
#define BUFS 30720
#define SMSZ 61952

struct Frag { uint4 aH0, aH1, aL0, aL1, bH0, bL0; };

__device__ __forceinline__ void loadOps(
    const char* qAH, const char* qAL, const char* qBH, const char* qBL,
    size_t arow_off, bool av, size_t brow_off, bool bv, int kt, int tid, Frag& f) {
    uint4 zz = make_uint4(0, 0, 0, 0);
    const char* pa = qAH + arow_off + kt + (tid & 1) * 32;
    const char* pl = qAL + arow_off + kt + (tid & 1) * 32;
    f.aH0 = av ? *(const uint4*)pa : zz;
    f.aH1 = av ? *(const uint4*)(pa + 16) : zz;
    f.aL0 = av ? *(const uint4*)pl : zz;
    f.aL1 = av ? *(const uint4*)(pl + 16) : zz;
    const char* pb = qBH + brow_off + kt + (tid & 3) * 16;
    const char* pbl = qBL + brow_off + kt + (tid & 3) * 16;
    f.bH0 = bv ? *(const uint4*)pb : zz;
    f.bL0 = bv ? *(const uint4*)pbl : zz;
}
__device__ __forceinline__ void stsOps(char* sm, int buf, int tid, const Frag& f) {
    char* b = sm + buf * BUFS;
    int ar = tid >> 1, ac = (tid & 1) * 32;
    *(uint4*)(b + ar * 80 + ac) = f.aH0;
    *(uint4*)(b + ar * 80 + ac + 16) = f.aH1;
    *(uint4*)(b + ABUF + ar * 80 + ac) = f.aL0;
    *(uint4*)(b + ABUF + ar * 80 + ac + 16) = f.aL1;
    int br = tid >> 2, bc = (tid & 3) * 16;
    *(uint4*)(b + 2 * ABUF + br * 80 + bc) = f.bH0;
    *(uint4*)(b + 2 * ABUF + BBUF + br * 80 + bc) = f.bL0;
}
__device__ __forceinline__ void immaSlab(const char* sm, int buf,
                                         int accA[4][2][4], int accB[4][2][4],
                                         int wm, int wn, int gid, int tig) {
    const char* AH = sm + buf * BUFS;
    const char* AL = AH + ABUF;
    const char* BH = AH + 2 * ABUF;
    const char* BL = BH + BBUF;
#pragma unroll
    for (int ks = 0; ks < 2; ks++) {
        int kb = ks * 32 + 4 * tig;
        unsigned bh[2][2], bl[2][2];
#pragma unroll
        for (int nj = 0; nj < 2; nj++) {
            int nr = wn * 16 + nj * 8 + gid;
            bh[nj][0] = *(const unsigned*)(BH + nr * 80 + kb);
            bh[nj][1] = *(const unsigned*)(BH + nr * 80 + kb + 16);
            bl[nj][0] = *(const unsigned*)(BL + nr * 80 + kb);
            bl[nj][1] = *(const unsigned*)(BL + nr * 80 + kb + 16);
        }
#pragma unroll
        for (int mi = 0; mi < 4; mi++) {
            int r0 = wm * 64 + mi * 16 + gid;
            unsigned ah[4], al[4];
            ah[0] = *(const unsigned*)(AH + r0 * 80 + kb);
            ah[1] = *(const unsigned*)(AH + (r0 + 8) * 80 + kb);
            ah[2] = *(const unsigned*)(AH + r0 * 80 + kb + 16);
            ah[3] = *(const unsigned*)(AH + (r0 + 8) * 80 + kb + 16);
            al[0] = *(const unsigned*)(AL + r0 * 80 + kb);
            al[1] = *(const unsigned*)(AL + (r0 + 8) * 80 + kb);
            al[2] = *(const unsigned*)(AL + r0 * 80 + kb + 16);
            al[3] = *(const unsigned*)(AL + (r0 + 8) * 80 + kb + 16);
#pragma unroll
            for (int nj = 0; nj < 2; nj++) {
                imma(accA[mi][nj], ah, bh[nj]);
                imma(accB[mi][nj], ah, bl[nj]);
                imma(accB[mi][nj], al, bh[nj]);
            }
        }
    }
}

// ---- GEMM1: d_hh[z] = agg[z] @ Wa[z] + ba[z]; fused stats ----
__global__ __launch_bounds__(256) void k_gemm1(const float* __restrict__ ba,
                                               int M, int KP, int Nd) {
    extern __shared__ char sm[];
    int tid = threadIdx.x;
    int lane = tid & 31, wid = tid >> 5;
    int wm = wid & 1, wn = wid >> 1;
    int gid = lane >> 2, tig = lane & 3;
    int z = blockIdx.z;
    int row0 = blockIdx.y * 128, col0 = blockIdx.x * 64;

    int accA[4][2][4], accB[4][2][4];
#pragma unroll
    for (int a = 0; a < 4; a++)
#pragma unroll
        for (int b = 0; b < 2; b++)
#pragma unroll
            for (int r = 0; r < 4; r++) { accA[a][b][r] = 0; accB[a][b][r] = 0; }

    int rowA = row0 + (tid >> 1);
    bool av = rowA < M;
    int nB = col0 + (tid >> 2);
    bool bv = nB < Nd;
    size_t aoff = ((size_t)z * NN + (av ? rowA : 0)) * 256;
    size_t boff = ((size_t)z * 512 + (bv ? nB : 0)) * 256;

    int T = KP / 64;
    Frag f;
    loadOps(d_aggQH, d_aggQL, d_waQH, d_waQL, aoff, av, boff, bv, 0, tid, f);
    for (int t = 0; t < T; t++) {
        int buf = t & 1;
        stsOps(sm, buf, tid, f);
        __syncthreads();
        if (t + 1 < T)
            loadOps(d_aggQH, d_aggQL, d_waQH, d_waQL, aoff, av, boff, bv,
                    (t + 1) * 64, tid, f);
        immaSlab(sm, buf, accA, accB, wm, wn, gid, tig);
        __syncthreads();
    }

    float* sS = (float*)(sm + 61440);
    float* sQ = sS + 64;
    if (tid < 64) { sS[tid] = 0.f; sQ[tid] = 0.f; }
    __syncthreads();

    float colS[2][2] = {{0, 0}, {0, 0}}, colQ[2][2] = {{0, 0}, {0, 0}};
#pragma unroll
    for (int mi = 0; mi < 4; mi++)
#pragma unroll
        for (int nj = 0; nj < 2; nj++)
#pragma unroll
            for (int r = 0; r < 4; r++) {
                int row = row0 + wm * 64 + mi * 16 + gid + (r >> 1) * 8;
                int col = col0 + wn * 16 + nj * 8 + 2 * tig + (r & 1);
                if (row < M && col < Nd) {
                    float q = fmaf(65536.f, (float)accA[mi][nj][r],
                                   256.f * (float)accB[mi][nj][r]);
                    float v = q * d_sAgg[z * NN + row] * d_sWa[z * 512 + col] +
                              ba[z * Nd + col];
                    d_hh[((size_t)z * NN + row) * Nd + col] = v;
                    colS[nj][r & 1] += v;
                    colQ[nj][r & 1] += v * v;
                }
            }
#pragma unroll
    for (int nj = 0; nj < 2; nj++)
#pragma unroll
        for (int p = 0; p < 2; p++) {
            int lc = wn * 16 + nj * 8 + 2 * tig + p;
            atomicAdd(&sS[lc], colS[nj][p]);
            atomicAdd(&sQ[lc], colQ[nj][p]);
        }
    __syncthreads();
    if (tid < 64) {
        int col = col0 + tid;
        if (col < Nd) {
            atomicAdd(&d_cs[z * 512 + col], sS[tid]);
            atomicAdd(&d_css[z * 512 + col], sQ[tid]);
        }
    }
}

// ---- BN finalize + h quantization ----
__global__ void k_bnfinal(const float* __restrict__ gB,
                          const float* __restrict__ btB, int C) {
    int k = blockIdx.x, c = threadIdx.x;
    if (c >= C) return;
    float mu = d_cs[k * 512 + c] / (float)NN;
    float var = d_css[k * 512 + c] / (float)NN - mu * mu;
    var = fmaxf(var, 0.f);
    float s = gB[k * C + c] * rsqrtf(var + BN_EPS);
    d_scale[k * 512 + c] = s;
    d_shift[k * 512 + c] = btB[k * C + c] - mu * s;
}
__global__ void k_qh(int ch) {
    int row = blockIdx.x, z = blockIdx.y, tid = threadIdx.x;
    float v0 = 0.f, v1 = 0.f;
    int c0 = tid, c1 = tid + 256;
    const float* hp = d_hh + ((size_t)z * NN + row) * ch;
    if (c0 < ch)
        v0 = fmaxf(fmaf(hp[c0], d_scale[z * 512 + c0], d_shift[z * 512 + c0]), 0.f);
    if (c1 < ch)
        v1 = fmaxf(fmaf(hp[c1], d_scale[z * 512 + c1], d_shift[z * 512 + c1]), 0.f);
    float M = blockMax256(fmaxf(v0, v1));
    float s = (M > 0.f) ? M / 32512.f : 1.f;
    float inv = 1.f / s;
    size_t ob = ((size_t)z * NN + row) * 512;
    char H = 0, L = 0;
    if (c0 < ch) q2(v0, inv, H, L);
    d_hQH[ob + c0] = H; d_hQL[ob + c0] = L;
    H = 0; L = 0;
    if (c1 < ch) q2(v1, inv, H, L);
    d_hQH[ob + c1] = H; d_hQL[ob + c1] = L;
    if (tid == 0) d_sH[z * NN + row] = s;
}

// ---- GEMM2: dest = act( sum_z hq[z] @ Wb[z] + sum bb ) ----
__global__ __launch_bounds__(256) void k_gemm2(const float* __restrict__ bb,
                                               float* __restrict__ dest, int M,
                                               int KP, int leaky) {
    extern __shared__ char sm[];
    int tid = threadIdx.x;
    int lane = tid & 31, wid = tid >> 5;
    int wm = wid & 1, wn = wid >> 1;
    int gid = lane >> 2, tig = lane & 3;
    int row0 = blockIdx.y * 128, col0 = blockIdx.x * 64;

    float Cf[4][2][4];
#pragma unroll
    for (int a = 0; a < 4; a++)
#pragma unroll
        for (int b = 0; b < 2; b++)
#pragma unroll
            for (int r = 0; r < 4; r++) Cf[a][b][r] = 0.f;

    int rowA = row0 + (tid >> 1);
    bool av = rowA < M;
    int nB = col0 + (tid >> 2);   // always < 256
    int tz = KP / 64;

    for (int z = 0; z < KT; z++) {
        int accA[4][2][4], accB[4][2][4];
#pragma unroll
        for (int a = 0; a < 4; a++)
#pragma unroll
            for (int b = 0; b < 2; b++)
#pragma unroll
                for (int r = 0; r < 4; r++) { accA[a][b][r] = 0; accB[a][b][r] = 0; }
        size_t aoff = ((size_t)z * NN + (av ? rowA : 0)) * 512;
        size_t boff = ((size_t)z * 256 + nB) * 512;
        Frag f;
        loadOps(d_hQH, d_hQL, d_wbQH, d_wbQL, aoff, av, boff, true, 0, tid, f);
        for (int t = 0; t < tz; t++) {
            int buf = t & 1;
            stsOps(sm, buf, tid, f);
            __syncthreads();
            if (t + 1 < tz)
                loadOps(d_hQH, d_hQL, d_wbQH, d_wbQL, aoff, av, boff, true,
                        (t + 1) * 64, tid, f);
            immaSlab(sm, buf, accA, accB, wm, wn, gid, tig);
            __syncthreads();
        }
#pragma unroll
        for (int mi = 0; mi < 4; mi++)
#pragma unroll
            for (int nj = 0; nj < 2; nj++)
#pragma unroll
                for (int r = 0; r < 4; r++) {
                    int row = row0 + wm * 64 + mi * 16 + gid + (r >> 1) * 8;
                    int col = col0 + wn * 16 + nj * 8 + 2 * tig + (r & 1);
                    float sA = d_sH[z * NN + (row < M ? row : 0)];
                    float q = fmaf(65536.f, (float)accA[mi][nj][r],
                                   256.f * (float)accB[mi][nj][r]);
                    Cf[mi][nj][r] = fmaf(q, sA * d_sWb[z * 256 + col], Cf[mi][nj][r]);
                }
    }

#pragma unroll
    for (int mi = 0; mi < 4; mi++)
#pragma unroll
        for (int nj = 0; nj < 2; nj++)
#pragma unroll
            for (int r = 0; r < 4; r++) {
                int row = row0 + wm * 64 + mi * 16 + gid + (r >> 1) * 8;
                int col = col0 + wn * 16 + nj * 8 + 2 * tig + (r & 1);
                if (row < M) {
                    float v = Cf[mi][nj][r] + bb[col] + bb[256 + col] + bb[512 + col];
                    if (leaky) v = (v > 0.f) ? v : 0.01f * v;
                    dest[(size_t)row * 256 + col] = v;
                }
            }
}

// ---------------- launch ----------------
extern "C" void kernel_launch(void* const* d_in, const int* in_sizes, int n_in,
                              void* d_out, int out_size) {
    float* p_xcur;   // GB300 ATS pitfall: resolve real device address
    cudaGetSymbolAddress((void**)&p_xcur, d_xcur);
    cudaFuncSetAttribute(k_gemm1, cudaFuncAttributeMaxDynamicSharedMemorySize, SMSZ);
    cudaFuncSetAttribute(k_gemm2, cudaFuncAttributeMaxDynamicSharedMemorySize, SMSZ);

    const float* x = (const float*)d_in[0];
    const int* ei = (const int*)d_in[1];
    const float* ea = (const float*)d_in[2];

    const int ciL[3] = {170, 256, 256};
    const int chL[3] = {340, 512, 512};

    k_count<<<(KT * NE + 255) / 256, 256>>>(ei);
    k_scan<<<KT, 1024>>>();
    k_fill<<<(KT * NE + 255) / 256, 256>>>(ei);

    const float* xin = x;
    for (int l = 0; l < 3; l++) {
        int ci = ciL[l], ch = chL[l];
        int KP1 = (ci + 63) & ~63;
        int KP2 = (ch + 63) & ~63;
        const float* We = (const float*)d_in[3 + l * 8 + 0];
        const float* be = (const float*)d_in[3 + l * 8 + 1];
        const float* Wa = (const float*)d_in[3 + l * 8 + 2];
        const float* ba = (const float*)d_in[3 + l * 8 + 3];
        const float* g  = (const float*)d_in[3 + l * 8 + 4];
        const float* bt = (const float*)d_in[3 + l * 8 + 5];
        const float* Wb = (const float*)d_in[3 + l * 8 + 6];
        const float* bb = (const float*)d_in[3 + l * 8 + 7];
        float* dest = (l == 2) ? (float*)d_out : p_xcur;

        k_qw<<<dim3(ch, KT), 256>>>(Wa, ci, ch, 0);
        k_qw<<<dim3(256, KT), 256>>>(Wb, ch, 256, 1);

        k_aggr<<<dim3(NN, KT), 256>>>(xin, ei, ea, We, be, ci);

        dim3 g1((ch + 63) / 64, (NN + 127) / 128, KT);
        k_gemm1<<<g1, 256, SMSZ>>>(ba, NN, KP1, ch);

        k_bnfinal<<<KT, 512>>>(g, bt, ch);
        k_qh<<<dim3(NN, KT), 256>>>(ch);

        dim3 g2(4, (NN + 127) / 128);
        k_gemm2<<<g2, 256, SMSZ>>>(bb, dest, NN, KP2, (l < 2) ? 1 : 0);

        if (l < 2) xin = p_xcur;
    }
}

// round 15
// speedup vs baseline: 1.7453x; 1.7453x over previous
#include <cuda_runtime.h>
#include <cuda_bf16.h>
#include <cstdint>

#define NN 16500
#define NE 100000
#define KT 3
#define GEN_EPS 1e-7f
#define BN_EPS 1e-5f

// ---------------- scratch ----------------
__device__ int d_cnt[KT][NN];
__device__ int d_off[KT][NN + 1];
__device__ int d_cur[KT][NN];
__device__ int d_eid[KT][NE];
__device__ float d_hh[(size_t)KT * NN * 512];     // GEMM1 out f32, stride=ch
__device__ float d_xcur[NN * 256];
__device__ float d_cs[KT * 512], d_css[KT * 512];
__device__ float d_scale[KT * 512], d_shift[KT * 512];
// planar bf16 hi/lo operands (K zero-padded to fixed strides)
__device__ __nv_bfloat16 d_aggH[(size_t)KT * NN * 256];   // stride 256
__device__ __nv_bfloat16 d_aggL[(size_t)KT * NN * 256];
__device__ __nv_bfloat16 d_hH[(size_t)KT * NN * 512];     // stride 512
__device__ __nv_bfloat16 d_hL[(size_t)KT * NN * 512];
__device__ __nv_bfloat16 d_waH[(size_t)KT * 512 * 256];   // [z][n<=512][k s256]
__device__ __nv_bfloat16 d_waL[(size_t)KT * 512 * 256];
__device__ __nv_bfloat16 d_wbH[(size_t)KT * 256 * 512];   // [z][n<256][k s512]
__device__ __nv_bfloat16 d_wbL[(size_t)KT * 256 * 512];

__device__ __forceinline__ void split_bf16(float v, __nv_bfloat16& hi,
                                           __nv_bfloat16& lo) {
    hi = __float2bfloat16(v);
    lo = __float2bfloat16(v - __bfloat162float(hi));
}
__device__ __forceinline__ uint32_t smem_u32(const void* p) {
    uint32_t a;
    asm("{ .reg .u64 t; cvta.to.shared.u64 t, %1; cvt.u32.u64 %0, t; }"
        : "=r"(a) : "l"(p));
    return a;
}
__device__ __forceinline__ void cpa16(uint32_t dst, const void* src) {
    asm volatile("cp.async.ca.shared.global [%0], [%1], 16;"
                 :: "r"(dst), "l"(src));
}
#define CP_COMMIT() asm volatile("cp.async.commit_group;" ::: "memory")
#define CP_WAIT0()  asm volatile("cp.async.wait_group 0;" ::: "memory")
__device__ __forceinline__ void ldsm4(unsigned r[4], uint32_t a) {
    asm volatile("ldmatrix.sync.aligned.m8n8.x4.shared.b16 {%0,%1,%2,%3}, [%4];"
                 : "=r"(r[0]), "=r"(r[1]), "=r"(r[2]), "=r"(r[3]) : "r"(a));
}
__device__ __forceinline__ void mma_bf16(float* c, const unsigned* a,
                                         const unsigned* b) {
    asm volatile(
        "mma.sync.aligned.m16n8k16.row.col.f32.bf16.bf16.f32 "
        "{%0,%1,%2,%3}, {%4,%5,%6,%7}, {%8,%9}, {%0,%1,%2,%3};"
        : "+f"(c[0]), "+f"(c[1]), "+f"(c[2]), "+f"(c[3])
        : "r"(a[0]), "r"(a[1]), "r"(a[2]), "r"(a[3]), "r"(b[0]), "r"(b[1]));
}

// ---------------- CSR build ----------------
__global__ void k_count(const int* __restrict__ ei) {
    int i = blockIdx.x * blockDim.x + threadIdx.x;
    if (i >= KT * NE) return;
    int k = i / NE, e = i % NE;
    atomicAdd(&d_cnt[k][ei[k * 2 * NE + NE + e]], 1);
}
__global__ void k_scan() {
    __shared__ int sh[1024];
    int k = blockIdx.x, tid = threadIdx.x;
    int carry = 0;
    if (tid == 0) d_off[k][0] = 0;
    for (int base = 0; base < NN; base += 1024) {
        int i = base + tid;
        int v = (i < NN) ? d_cnt[k][i] : 0;
        sh[tid] = v;
        __syncthreads();
        for (int o = 1; o < 1024; o <<= 1) {
            int t = (tid >= o) ? sh[tid - o] : 0;
            __syncthreads();
            sh[tid] += t;
            __syncthreads();
        }
        int inc = sh[tid], tot = sh[1023];
        if (i < NN) {
            d_off[k][i + 1] = carry + inc;
            d_cur[k][i] = carry + inc - v;
        }
        __syncthreads();
        carry += tot;
    }
}
__global__ void k_fill(const int* __restrict__ ei) {
    int i = blockIdx.x * blockDim.x + threadIdx.x;
    if (i < KT * NE) {
        int k = i / NE, e = i % NE;
        int pos = atomicAdd(&d_cur[k][ei[k * 2 * NE + NE + e]], 1);
        d_eid[k][pos] = e;
    }
    if (i < KT * NN) ((int*)d_cnt)[i] = 0;
}

// ---- weight split + transpose to planar [z][n][k-padded] ----
__global__ void k_wsplitA(const float* __restrict__ W, int Kd, int Nd) {
    int i = blockIdx.x * blockDim.x + threadIdx.x;
    if (i >= KT * Nd * 256) return;
    int k = i & 255;
    int n = (i >> 8) % Nd;
    int z = i / (Nd * 256);
    float v = (k < Kd) ? W[((size_t)z * Kd + k) * Nd + n] : 0.f;
    __nv_bfloat16 h, l;
    split_bf16(v, h, l);
    size_t o = ((size_t)z * 512 + n) * 256 + k;
    d_waH[o] = h; d_waL[o] = l;
}
__global__ void k_wsplitB(const float* __restrict__ W, int Kd) {
    int i = blockIdx.x * blockDim.x + threadIdx.x;
    if (i >= KT * 256 * 512) return;
    int k = i & 511;
    int n = (i >> 9) & 255;
    int z = i / (256 * 512);
    float v = (k < Kd) ? W[((size_t)z * Kd + k) * 256 + n] : 0.f;
    __nv_bfloat16 h, l;
    split_bf16(v, h, l);
    d_wbH[i] = h; d_wbL[i] = l;
}

// ---- aggregation (no-max softmax) + planar split output ----
__global__ void k_aggr(const float* __restrict__ xin,
                       const int* __restrict__ ei,
                       const float* __restrict__ ea,
                       const float* __restrict__ WeB,
                       const float* __restrict__ beB, int ci) {
    __shared__ int s_src[192];
    __shared__ float s_a[192];
    int n = blockIdx.x, z = blockIdx.y, tid = threadIdx.x;
    if (n == 0) {
        for (int i = tid; i < 512; i += 256) {
            d_cs[z * 512 + i] = 0.f;
            d_css[z * 512 + i] = 0.f;
        }
    }
    int j0 = d_off[z][n];
    int deg = d_off[z][n + 1] - j0;
    int cap = min(deg, 192);
    const int* src = ei + z * 2 * NE;
    const float* eak = ea + z * NE;
    for (int j = tid; j < cap; j += 256) {
        int e = d_eid[z][j0 + j];
        s_src[j] = src[e];
        s_a[j] = eak[e];
    }
    __syncthreads();
    int c = tid;
    float res = 0.f;
    if (c < ci) {
        float we = WeB[z * ci + c], bec = beB[z * ci + c];
        float xn = xin[n * ci + c];
        float u0 = fmaxf(xn + we + bec, 0.f) + GEN_EPS;
        float den = __expf(u0);
        float ws = u0 * den;
#pragma unroll 4
        for (int j = 0; j < cap; j++) {
            float u = fmaxf(xin[s_src[j] * ci + c] + s_a[j] * we + bec, 0.f) + GEN_EPS;
            float e = __expf(u);
            den += e;
            ws = fmaf(u, e, ws);
        }
        for (int jj = cap; jj < deg; jj++) {
            int e0 = d_eid[z][j0 + jj];
            float u = fmaxf(xin[src[e0] * ci + c] + eak[e0] * we + bec, 0.f) + GEN_EPS;
            float e = __expf(u);
            den += e;
            ws = fmaf(u, e, ws);
        }
        res = ws / den + xn;
    }
    __nv_bfloat16 h, l;
    split_bf16(res, h, l);
    size_t o = ((size_t)z * NN + n) * 256 + c;
    d_aggH[o] = h; d_aggL[o] = l;
}

// ---------------- GEMM machinery (BK=32, stride 80B, ldmatrix) ----------------
#define PL 10240   // one 128x32 bf16 plane (128 rows x 80B)

// cp.async fill of one plane: 128 rows x 32 bf16 (64B) from planar src
__device__ __forceinline__ void cp_plane(const __nv_bfloat16* __restrict__ src,
                                         uint32_t dstB, int row0, int rmax,
                                         int stride, int kt, int tid) {
    int q = tid & 3;            // 16B chunk (4 per row)
    int r = tid >> 2;           // rows r and r+64
#pragma unroll
    for (int it = 0; it < 2; it++) {
        int rr = r + it * 64;
        int rg = row0 + rr;
        if (rg >= rmax) rg = rmax - 1;   // clamp; garbage rows discarded later
        const void* s = src + (size_t)rg * stride + kt + q * 8;
        cpa16(dstB + rr * 80 + q * 16, s);
    }
}

__device__ __forceinline__ void mma_slab(uint32_t ahB, uint32_t alB,
                                         uint32_t bhB, uint32_t blB,
                                         float acc[4][4][4], uint32_t aoff,
                                         uint32_t boff) {
#pragma unroll
    for (int ks = 0; ks < 2; ks++) {
        unsigned bh[2][4], bl[2][4];
#pragma unroll
        for (int p = 0; p < 2; p++) {
            uint32_t ba = boff + p * (16 * 80) + ks * 32;
            ldsm4(bh[p], bhB + ba);
            ldsm4(bl[p], blB + ba);
        }
#pragma unroll
        for (int mi = 0; mi < 4; mi++) {
            uint32_t aa = aoff + mi * (16 * 80) + ks * 32;
            unsigned ah[4], al[4];
            ldsm4(ah, ahB + aa);
            ldsm4(al, alB + aa);
#pragma unroll
            for (int p = 0; p < 2; p++) {
                mma_bf16(acc[mi][2 * p], ah, &bh[p][0]);
                mma_bf16(acc[mi][2 * p], ah, &bl[p][0]);
                mma_bf16(acc[mi][2 * p], al, &bh[p][0]);
                mma_bf16(acc[mi][2 * p + 1], ah, &bh[p][2]);
                mma_bf16(acc[mi][2 * p + 1], ah, &bl[p][2]);
                mma_bf16(acc[mi][2 * p + 1], al, &bh[p][2]);
            }
        }
    }
}

// ---- GEMM1: d_hh[z] = agg[z] @ Wa[z] + ba[z]; fused stats ----
__global__ __launch_bounds__(256, 2) void k_gemm1(const float* __restrict__ ba,
                                                  int M, int KP, int Nd) {
    __shared__ __align__(16) char sm[4 * PL];
    __shared__ float sS[128], sQ[128];
    uint32_t base = smem_u32(sm);
    int tid = threadIdx.x;
    int lane = tid & 31, wid = tid >> 5;
    int wm = wid & 1, wn = wid >> 1;
    int gid = lane >> 2, tig = lane & 3;
    int z = blockIdx.z;
    int row0 = blockIdx.y * 128, col0 = blockIdx.x * 128;

    const __nv_bfloat16* aH = d_aggH + (size_t)z * NN * 256;
    const __nv_bfloat16* aL = d_aggL + (size_t)z * NN * 256;
    const __nv_bfloat16* bH = d_waH + (size_t)z * 512 * 256;
    const __nv_bfloat16* bL = d_waL + (size_t)z * 512 * 256;

    float acc[4][4][4];
#pragma unroll
    for (int a = 0; a < 4; a++)
#pragma unroll
        for (int b = 0; b < 4; b++)
#pragma unroll
            for (int r = 0; r < 4; r++) acc[a][b][r] = 0.f;

    uint32_t aoff = (uint32_t)((wm * 64 + (lane & 7) + ((lane >> 3) & 1) * 8) * 80 +
                               (lane >> 4) * 16);
    uint32_t boff = (uint32_t)((wn * 32 + (lane & 7) + (lane >> 4) * 8) * 80 +
                               ((lane >> 3) & 1) * 16);

    int T = KP / 32;
    for (int t = 0; t < T; t++) {
        int kt = t * 32;
        cp_plane(aH, base, row0, M, 256, kt, tid);
        cp_plane(aL, base + PL, row0, M, 256, kt, tid);
        cp_plane(bH, base + 2 * PL, col0, 512, 256, kt, tid);
        cp_plane(bL, base + 3 * PL, col0, 512, 256, kt, tid);
        CP_COMMIT();
        CP_WAIT0();
        __syncthreads();
        mma_slab(base, base + PL, base + 2 * PL, base + 3 * PL, acc, aoff, boff);
        __syncthreads();
    }

    if (tid < 128) { sS[tid] = 0.f; sQ[tid] = 0.f; }
    __syncthreads();
    float colS[8], colQ[8];
#pragma unroll
    for (int i = 0; i < 8; i++) { colS[i] = 0.f; colQ[i] = 0.f; }
#pragma unroll
    for (int mi = 0; mi < 4; mi++)
#pragma unroll
        for (int nj = 0; nj < 4; nj++)
#pragma unroll
            for (int r = 0; r < 4; r++) {
                int row = row0 + wm * 64 + mi * 16 + gid + (r >> 1) * 8;
                int col = col0 + wn * 32 + nj * 8 + 2 * tig + (r & 1);
                if (row < M && col < Nd) {
                    float v = acc[mi][nj][r] + ba[z * Nd + col];
                    d_hh[((size_t)z * NN + row) * Nd + col] = v;
                    int i2 = nj * 2 + (r & 1);
                    colS[i2] += v;
                    colQ[i2] += v * v;
                }
            }
#pragma unroll
    for (int i = 0; i < 8; i++) {
        int lc = wn * 32 + (i >> 1) * 8 + 2 * tig + (i & 1);
        atomicAdd(&sS[lc], colS[i]);
        atomicAdd(&sQ[lc], colQ[i]);
    }
    __syncthreads();
    if (tid < 128) {
        int col = col0 + tid;
        if (col < Nd) {
            atomicAdd(&d_cs[z * 512 + col], sS[tid]);
            atomicAdd(&d_css[z * 512 + col], sQ[tid]);
        }
    }
}

// ---- BN finalize + h convert (BN+ReLU+split, zero-padded stride 512) ----
__global__ void k_bnfinal(const float* __restrict__ gB,
                          const float* __restrict__ btB, int C) {
    int k = blockIdx.x, c = threadIdx.x;
    if (c >= C) return;
    float mu = d_cs[k * 512 + c] / (float)NN;
    float var = d_css[k * 512 + c] / (float)NN - mu * mu;
    var = fmaxf(var, 0.f);
    float s = gB[k * C + c] * rsqrtf(var + BN_EPS);
    d_scale[k * 512 + c] = s;
    d_shift[k * 512 + c] = btB[k * C + c] - mu * s;
}
__global__ void k_hcvt(int ch) {
    int i = blockIdx.x * blockDim.x + threadIdx.x;
    if (i >= KT * NN * 512) return;
    int c = i & 511;
    int row = (i >> 9) % NN;
    int z = i / (NN * 512);
    float v = 0.f;
    if (c < ch) {
        v = d_hh[((size_t)z * NN + row) * ch + c];
        v = fmaxf(fmaf(v, d_scale[z * 512 + c], d_shift[z * 512 + c]), 0.f);
    }
    __nv_bfloat16 h, l;
    split_bf16(v, h, l);
    d_hH[i] = h; d_hL[i] = l;
}

// ---- GEMM2: dest = act( sum_z h[z] @ Wb[z] + sum bb ) ----
__global__ __launch_bounds__(256, 2) void k_gemm2(const float* __restrict__ bb,
                                                  float* __restrict__ dest,
                                                  int M, int KP, int leaky) {
    __shared__ __align__(16) char sm[4 * PL];
    uint32_t base = smem_u32(sm);
    int tid = threadIdx.x;
    int lane = tid & 31, wid = tid >> 5;
    int wm = wid & 1, wn = wid >> 1;
    int gid = lane >> 2, tig = lane & 3;
    int row0 = blockIdx.y * 128, col0 = blockIdx.x * 128;

    float acc[4][4][4];
#pragma unroll
    for (int a = 0; a < 4; a++)
#pragma unroll
        for (int b = 0; b < 4; b++)
#pragma unroll
            for (int r = 0; r < 4; r++) acc[a][b][r] = 0.f;

    uint32_t aoff = (uint32_t)((wm * 64 + (lane & 7) + ((lane >> 3) & 1) * 8) * 80 +
                               (lane >> 4) * 16);
    uint32_t boff = (uint32_t)((wn * 32 + (lane & 7) + (lane >> 4) * 8) * 80 +
                               ((lane >> 3) & 1) * 16);

    int T = KP / 32;
    for (int z = 0; z < KT; z++) {
        const __nv_bfloat16* aH = d_hH + (size_t)z * NN * 512;
        const __nv_bfloat16* aL = d_hL + (size_t)z * NN * 512;
        const __nv_bfloat16* bH = d_wbH + (size_t)z * 256 * 512;
        const __nv_bfloat16* bL = d_wbL + (size_t)z * 256 * 512;
        for (int t = 0; t < T; t++) {
            int kt = t * 32;
            cp_plane(aH, base, row0, M, 512, kt, tid);
            cp_plane(aL, base + PL, row0, M, 512, kt, tid);
            cp_plane(bH, base + 2 * PL, col0, 256, 512, kt, tid);
            cp_plane(bL, base + 3 * PL, col0, 256, 512, kt, tid);
            CP_COMMIT();
            CP_WAIT0();
            __syncthreads();
            mma_slab(base, base + PL, base + 2 * PL, base + 3 * PL, acc, aoff,
                     boff);
            __syncthreads();
        }
    }

#pragma unroll
    for (int mi = 0; mi < 4; mi++)
#pragma unroll
        for (int nj = 0; nj < 4; nj++)
#pragma unroll
            for (int r = 0; r < 4; r++) {
                int row = row0 + wm * 64 + mi * 16 + gid + (r >> 1) * 8;
                int col = col0 + wn * 32 + nj * 8 + 2 * tig + (r & 1);
                if (row < M && col < 256) {
                    float v = acc[mi][nj][r] + bb[col] + bb[256 + col] +
                              bb[512 + col];
                    if (leaky) v = (v > 0.f) ? v : 0.01f * v;
                    dest[(size_t)row * 256 + col] = v;
                }
            }
}

// ---------------- launch ----------------
extern "C" void kernel_launch(void* const* d_in, const int* in_sizes, int n_in,
                              void* d_out, int out_size) {
    float* p_xcur;   // GB300 ATS pitfall: resolve real device address
    cudaGetSymbolAddress((void**)&p_xcur, d_xcur);

    const float* x = (const float*)d_in[0];
    const int* ei = (const int*)d_in[1];
    const float* ea = (const float*)d_in[2];

    const int ciL[3] = {170, 256, 256};
    const int chL[3] = {340, 512, 512};

    k_count<<<(KT * NE + 255) / 256, 256>>>(ei);
    k_scan<<<KT, 1024>>>();
    k_fill<<<(KT * NE + 255) / 256, 256>>>(ei);

    const float* xin = x;
    for (int l = 0; l < 3; l++) {
        int ci = ciL[l], ch = chL[l];
        int KP1 = (ci + 31) & ~31;    // 192 / 256
        int KP2 = (ch + 31) & ~31;    // 352? -> 340+31 = 371 & ~31 = 352
        const float* We = (const float*)d_in[3 + l * 8 + 0];
        const float* be = (const float*)d_in[3 + l * 8 + 1];
        const float* Wa = (const float*)d_in[3 + l * 8 + 2];
        const float* ba = (const float*)d_in[3 + l * 8 + 3];
        const float* g  = (const float*)d_in[3 + l * 8 + 4];
        const float* bt = (const float*)d_in[3 + l * 8 + 5];
        const float* Wb = (const float*)d_in[3 + l * 8 + 6];
        const float* bb = (const float*)d_in[3 + l * 8 + 7];
        float* dest = (l == 2) ? (float*)d_out : p_xcur;

        int na = KT * ch * 256;
        k_wsplitA<<<(na + 255) / 256, 256>>>(Wa, ci, ch);
        int nb = KT * 256 * 512;
        k_wsplitB<<<(nb + 255) / 256, 256>>>(Wb, ch);

        k_aggr<<<dim3(NN, KT), 256>>>(xin, ei, ea, We, be, ci);

        dim3 g1((ch + 127) / 128, (NN + 127) / 128, KT);
        k_gemm1<<<g1, 256>>>(ba, NN, KP1, ch);

        k_bnfinal<<<KT, 512>>>(g, bt, ch);
        int nh = KT * NN * 512;
        k_hcvt<<<(nh + 255) / 256, 256>>>(ch);

        dim3 g2(2, (NN + 127) / 128);
        k_gemm2<<<g2, 256>>>(bb, dest, NN, KP2, (l < 2) ? 1 : 0);

        if (l < 2) xin = p_xcur;
    }
}

// round 16
// speedup vs baseline: 1.8661x; 1.0692x over previous
#include <cuda_runtime.h>
#include <cuda_bf16.h>
#include <cstdint>

#define NN 16500
#define NE 100000
#define KT 3
#define GEN_EPS 1e-7f
#define BN_EPS 1e-5f

// ---------------- scratch ----------------
__device__ int d_cnt[KT][NN];
__device__ int d_off[KT][NN + 1];
__device__ int d_cur[KT][NN];
__device__ int d_eid[KT][NE];
__device__ float d_hh[(size_t)KT * NN * 512];     // GEMM1 out f32, stride=ch
__device__ float d_xcur[NN * 256];
__device__ float d_cs[KT * 512], d_css[KT * 512];
__device__ float d_scale[KT * 512], d_shift[KT * 512];
// planar bf16 hi/lo operands (K zero-padded to fixed strides)
__device__ __nv_bfloat16 d_aggH[(size_t)KT * NN * 256];   // stride 256
__device__ __nv_bfloat16 d_aggL[(size_t)KT * NN * 256];
__device__ __nv_bfloat16 d_hH[(size_t)KT * NN * 512];     // stride 512
__device__ __nv_bfloat16 d_hL[(size_t)KT * NN * 512];
__device__ __nv_bfloat16 d_waH[(size_t)KT * 512 * 256];   // [z][n<=512][k s256]
__device__ __nv_bfloat16 d_waL[(size_t)KT * 512 * 256];
__device__ __nv_bfloat16 d_wbH[(size_t)KT * 256 * 512];   // [z][n<256][k s512]
__device__ __nv_bfloat16 d_wbL[(size_t)KT * 256 * 512];

__device__ __forceinline__ void split_bf16(float v, __nv_bfloat16& hi,
                                           __nv_bfloat16& lo) {
    hi = __float2bfloat16(v);
    lo = __float2bfloat16(v - __bfloat162float(hi));
}
__device__ __forceinline__ uint32_t smem_u32(const void* p) {
    uint32_t a;
    asm("{ .reg .u64 t; cvta.to.shared.u64 t, %1; cvt.u32.u64 %0, t; }"
        : "=r"(a) : "l"(p));
    return a;
}
__device__ __forceinline__ void cpa16(uint32_t dst, const void* src) {
    asm volatile("cp.async.ca.shared.global [%0], [%1], 16;"
                 :: "r"(dst), "l"(src));
}
#define CP_COMMIT() asm volatile("cp.async.commit_group;" ::: "memory")
#define CP_WAIT0()  asm volatile("cp.async.wait_group 0;" ::: "memory")
#define CP_WAIT1()  asm volatile("cp.async.wait_group 1;" ::: "memory")
__device__ __forceinline__ void ldsm4(unsigned r[4], uint32_t a) {
    asm volatile("ldmatrix.sync.aligned.m8n8.x4.shared.b16 {%0,%1,%2,%3}, [%4];"
                 : "=r"(r[0]), "=r"(r[1]), "=r"(r[2]), "=r"(r[3]) : "r"(a));
}
__device__ __forceinline__ void mma_bf16(float* c, const unsigned* a,
                                         const unsigned* b) {
    asm volatile(
        "mma.sync.aligned.m16n8k16.row.col.f32.bf16.bf16.f32 "
        "{%0,%1,%2,%3}, {%4,%5,%6,%7}, {%8,%9}, {%0,%1,%2,%3};"
        : "+f"(c[0]), "+f"(c[1]), "+f"(c[2]), "+f"(c[3])
        : "r"(a[0]), "r"(a[1]), "r"(a[2]), "r"(a[3]), "r"(b[0]), "r"(b[1]));
}

// ---------------- CSR build ----------------
__global__ void k_count(const int* __restrict__ ei) {
    int i = blockIdx.x * blockDim.x + threadIdx.x;
    if (i >= KT * NE) return;
    int k = i / NE, e = i % NE;
    atomicAdd(&d_cnt[k][ei[k * 2 * NE + NE + e]], 1);
}
__global__ void k_scan() {
    __shared__ int sh[1024];
    int k = blockIdx.x, tid = threadIdx.x;
    int carry = 0;
    if (tid == 0) d_off[k][0] = 0;
    for (int base = 0; base < NN; base += 1024) {
        int i = base + tid;
        int v = (i < NN) ? d_cnt[k][i] : 0;
        sh[tid] = v;
        __syncthreads();
        for (int o = 1; o < 1024; o <<= 1) {
            int t = (tid >= o) ? sh[tid - o] : 0;
            __syncthreads();
            sh[tid] += t;
            __syncthreads();
        }
        int inc = sh[tid], tot = sh[1023];
        if (i < NN) {
            d_off[k][i + 1] = carry + inc;
            d_cur[k][i] = carry + inc - v;
        }
        __syncthreads();
        carry += tot;
    }
}
__global__ void k_fill(const int* __restrict__ ei) {
    int i = blockIdx.x * blockDim.x + threadIdx.x;
    if (i < KT * NE) {
        int k = i / NE, e = i % NE;
        int pos = atomicAdd(&d_cur[k][ei[k * 2 * NE + NE + e]], 1);
        d_eid[k][pos] = e;
    }
    if (i < KT * NN) ((int*)d_cnt)[i] = 0;
}

// ---- weight split + transpose to planar [z][n][k-padded] ----
__global__ void k_wsplitA(const float* __restrict__ W, int Kd, int Nd) {
    int i = blockIdx.x * blockDim.x + threadIdx.x;
    if (i >= KT * Nd * 256) return;
    int k = i & 255;
    int n = (i >> 8) % Nd;
    int z = i / (Nd * 256);
    float v = (k < Kd) ? W[((size_t)z * Kd + k) * Nd + n] : 0.f;
    __nv_bfloat16 h, l;
    split_bf16(v, h, l);
    size_t o = ((size_t)z * 512 + n) * 256 + k;
    d_waH[o] = h; d_waL[o] = l;
}
__global__ void k_wsplitB(const float* __restrict__ W, int Kd) {
    int i = blockIdx.x * blockDim.x + threadIdx.x;
    if (i >= KT * 256 * 512) return;
    int k = i & 511;
    int n = (i >> 9) & 255;
    int z = i / (256 * 512);
    float v = (k < Kd) ? W[((size_t)z * Kd + k) * 256 + n] : 0.f;
    __nv_bfloat16 h, l;
    split_bf16(v, h, l);
    d_wbH[i] = h; d_wbL[i] = l;
}

// ---- aggregation (no-max softmax) + planar split output ----
__global__ void k_aggr(const float* __restrict__ xin,
                       const int* __restrict__ ei,
                       const float* __restrict__ ea,
                       const float* __restrict__ WeB,
                       const float* __restrict__ beB, int ci) {
    __shared__ int s_src[192];
    __shared__ float s_a[192];
    int n = blockIdx.x, z = blockIdx.y, tid = threadIdx.x;
    if (n == 0) {
        for (int i = tid; i < 512; i += 256) {
            d_cs[z * 512 + i] = 0.f;
            d_css[z * 512 + i] = 0.f;
        }
    }
    int j0 = d_off[z][n];
    int deg = d_off[z][n + 1] - j0;
    int cap = min(deg, 192);
    const int* src = ei + z * 2 * NE;
    const float* eak = ea + z * NE;
    for (int j = tid; j < cap; j += 256) {
        int e = d_eid[z][j0 + j];
        s_src[j] = src[e];
        s_a[j] = eak[e];
    }
    __syncthreads();
    int c = tid;
    float res = 0.f;
    if (c < ci) {
        float we = WeB[z * ci + c], bec = beB[z * ci + c];
        float xn = xin[n * ci + c];
        float u0 = fmaxf(xn + we + bec, 0.f) + GEN_EPS;
        float den = __expf(u0);
        float ws = u0 * den;
#pragma unroll 4
        for (int j = 0; j < cap; j++) {
            float u = fmaxf(xin[s_src[j] * ci + c] + s_a[j] * we + bec, 0.f) + GEN_EPS;
            float e = __expf(u);
            den += e;
            ws = fmaf(u, e, ws);
        }
        for (int jj = cap; jj < deg; jj++) {
            int e0 = d_eid[z][j0 + jj];
            float u = fmaxf(xin[src[e0] * ci + c] + eak[e0] * we + bec, 0.f) + GEN_EPS;
            float e = __expf(u);
            den += e;
            ws = fmaf(u, e, ws);
        }
        res = ws / den + xn;
    }
    __nv_bfloat16 h, l;
    split_bf16(res, h, l);
    size_t o = ((size_t)z * NN + n) * 256 + c;
    d_aggH[o] = h; d_aggL[o] = l;
}

// ---------------- GEMM machinery (BK=32, stride 80B, ldmatrix) ----------------
#define PL 10240            // one 128x32 bf16 plane (128 rows x 80B)
#define STG (4 * PL)        // one pipeline stage = 4 planes
#define SMEMSZ (2 * STG + 1024)

__device__ __forceinline__ void cp_plane(const __nv_bfloat16* __restrict__ src,
                                         uint32_t dstB, int row0, int rmax,
                                         int stride, int kt, int tid) {
    int q = tid & 3;
    int r = tid >> 2;
#pragma unroll
    for (int it = 0; it < 2; it++) {
        int rr = r + it * 64;
        int rg = row0 + rr;
        if (rg >= rmax) rg = rmax - 1;   // clamp; garbage rows masked later
        const void* s = src + (size_t)rg * stride + kt + q * 8;
        cpa16(dstB + rr * 80 + q * 16, s);
    }
}

__device__ __forceinline__ void mma_slab(uint32_t ahB, uint32_t alB,
                                         uint32_t bhB, uint32_t blB,
                                         float acc[4][4][4], uint32_t aoff,
                                         uint32_t boff) {
#pragma unroll
    for (int ks = 0; ks < 2; ks++) {
        unsigned bh[2][4], bl[2][4];
#pragma unroll
        for (int p = 0; p < 2; p++) {
            uint32_t ba = boff + p * (16 * 80) + ks * 32;
            ldsm4(bh[p], bhB + ba);
            ldsm4(bl[p], blB + ba);
        }
#pragma unroll
        for (int mi = 0; mi < 4; mi++) {
            uint32_t aa = aoff + mi * (16 * 80) + ks * 32;
            unsigned ah[4], al[4];
            ldsm4(ah, ahB + aa);
            ldsm4(al, alB + aa);
#pragma unroll
            for (int p = 0; p < 2; p++) {
                mma_bf16(acc[mi][2 * p], ah, &bh[p][0]);
                mma_bf16(acc[mi][2 * p], ah, &bl[p][0]);
                mma_bf16(acc[mi][2 * p], al, &bh[p][0]);
                mma_bf16(acc[mi][2 * p + 1], ah, &bh[p][2]);
                mma_bf16(acc[mi][2 * p + 1], ah, &bl[p][2]);
                mma_bf16(acc[mi][2 * p + 1], al, &bh[p][2]);
            }
        }
    }
}

// ---- GEMM1: d_hh[z] = agg[z] @ Wa[z] + ba[z]; fused stats; pipelined ----
__global__ __launch_bounds__(256, 2) void k_gemm1(const float* __restrict__ ba,
                                                  int M, int KP, int Nd) {
    extern __shared__ __align__(16) char sm[];
    uint32_t base = smem_u32(sm);
    int tid = threadIdx.x;
    int lane = tid & 31, wid = tid >> 5;
    int wm = wid & 1, wn = wid >> 1;
    int gid = lane >> 2, tig = lane & 3;
    int z = blockIdx.z;
    int row0 = blockIdx.y * 128, col0 = blockIdx.x * 128;

    const __nv_bfloat16* aH = d_aggH + (size_t)z * NN * 256;
    const __nv_bfloat16* aL = d_aggL + (size_t)z * NN * 256;
    const __nv_bfloat16* bH = d_waH + (size_t)z * 512 * 256;
    const __nv_bfloat16* bL = d_waL + (size_t)z * 512 * 256;

    float acc[4][4][4];
#pragma unroll
    for (int a = 0; a < 4; a++)
#pragma unroll
        for (int b = 0; b < 4; b++)
#pragma unroll
            for (int r = 0; r < 4; r++) acc[a][b][r] = 0.f;

    uint32_t aoff = (uint32_t)((wm * 64 + (lane & 7) + ((lane >> 3) & 1) * 8) * 80 +
                               (lane >> 4) * 16);
    uint32_t boff = (uint32_t)((wn * 32 + (lane & 7) + (lane >> 4) * 8) * 80 +
                               ((lane >> 3) & 1) * 16);

    int T = KP / 32;
    auto issue = [&](int t) {
        uint32_t b = base + (t & 1) * STG;
        int kt = t * 32;
        cp_plane(aH, b, row0, M, 256, kt, tid);
        cp_plane(aL, b + PL, row0, M, 256, kt, tid);
        cp_plane(bH, b + 2 * PL, col0, 512, 256, kt, tid);
        cp_plane(bL, b + 3 * PL, col0, 512, 256, kt, tid);
        CP_COMMIT();
    };
    issue(0);
    for (int t = 0; t < T; t++) {
        if (t + 1 < T) { issue(t + 1); CP_WAIT1(); }
        else           { CP_WAIT0(); }
        __syncthreads();
        uint32_t b = base + (t & 1) * STG;
        mma_slab(b, b + PL, b + 2 * PL, b + 3 * PL, acc, aoff, boff);
        __syncthreads();
    }

    float* sS = (float*)(sm + 2 * STG);
    float* sQ = sS + 128;
    if (tid < 128) { sS[tid] = 0.f; sQ[tid] = 0.f; }
    __syncthreads();
    float colS[8], colQ[8];
#pragma unroll
    for (int i = 0; i < 8; i++) { colS[i] = 0.f; colQ[i] = 0.f; }
#pragma unroll
    for (int mi = 0; mi < 4; mi++)
#pragma unroll
        for (int nj = 0; nj < 4; nj++)
#pragma unroll
            for (int r = 0; r < 4; r++) {
                int row = row0 + wm * 64 + mi * 16 + gid + (r >> 1) * 8;
                int col = col0 + wn * 32 + nj * 8 + 2 * tig + (r & 1);
                if (row < M && col < Nd) {
                    float v = acc[mi][nj][r] + ba[z * Nd + col];
                    d_hh[((size_t)z * NN + row) * Nd + col] = v;
                    int i2 = nj * 2 + (r & 1);
                    colS[i2] += v;
                    colQ[i2] += v * v;
                }
            }
#pragma unroll
    for (int i = 0; i < 8; i++) {
        int lc = wn * 32 + (i >> 1) * 8 + 2 * tig + (i & 1);
        atomicAdd(&sS[lc], colS[i]);
        atomicAdd(&sQ[lc], colQ[i]);
    }
    __syncthreads();
    if (tid < 128) {
        int col = col0 + tid;
        if (col < Nd) {
            atomicAdd(&d_cs[z * 512 + col], sS[tid]);
            atomicAdd(&d_css[z * 512 + col], sQ[tid]);
        }
    }
}

// ---- BN finalize + vectorized h convert ----
__global__ void k_bnfinal(const float* __restrict__ gB,
                          const float* __restrict__ btB, int C) {
    int k = blockIdx.x, c = threadIdx.x;
    if (c >= C) return;
    float mu = d_cs[k * 512 + c] / (float)NN;
    float var = d_css[k * 512 + c] / (float)NN - mu * mu;
    var = fmaxf(var, 0.f);
    float s = gB[k * C + c] * rsqrtf(var + BN_EPS);
    d_scale[k * 512 + c] = s;
    d_shift[k * 512 + c] = btB[k * C + c] - mu * s;
}
__global__ void k_hcvt(int ch) {
    int i = blockIdx.x * blockDim.x + threadIdx.x;   // 4 channels / thread
    if (i >= KT * NN * 128) return;
    int c4 = (i & 127) * 4;
    int row = (i >> 7) % NN;
    int z = i / (NN * 128);
    float4 v = make_float4(0.f, 0.f, 0.f, 0.f);
    if (c4 < ch) {
        v = *(const float4*)(d_hh + ((size_t)z * NN + row) * ch + c4);
        const float* sc = d_scale + z * 512 + c4;
        const float* sh = d_shift + z * 512 + c4;
        v.x = fmaxf(fmaf(v.x, sc[0], sh[0]), 0.f);
        v.y = fmaxf(fmaf(v.y, sc[1], sh[1]), 0.f);
        v.z = fmaxf(fmaf(v.z, sc[2], sh[2]), 0.f);
        v.w = fmaxf(fmaf(v.w, sc[3], sh[3]), 0.f);
    }
    __nv_bfloat16 h[4], l[4];
    split_bf16(v.x, h[0], l[0]);
    split_bf16(v.y, h[1], l[1]);
    split_bf16(v.z, h[2], l[2]);
    split_bf16(v.w, h[3], l[3]);
    size_t o = ((size_t)z * NN + row) * 512 + c4;
    *(uint2*)(d_hH + o) = *(const uint2*)h;
    *(uint2*)(d_hL + o) = *(const uint2*)l;
}

// ---- GEMM2: dest = act( sum_z h[z] @ Wb[z] + sum bb ); pipelined over z,t ----
__global__ __launch_bounds__(256, 2) void k_gemm2(const float* __restrict__ bb,
                                                  float* __restrict__ dest,
                                                  int M, int KP, int leaky) {
    extern __shared__ __align__(16) char sm[];
    uint32_t base = smem_u32(sm);
    int tid = threadIdx.x;
    int lane = tid & 31, wid = tid >> 5;
    int wm = wid & 1, wn = wid >> 1;
    int gid = lane >> 2, tig = lane & 3;
    int row0 = blockIdx.y * 128, col0 = blockIdx.x * 128;

    float acc[4][4][4];
#pragma unroll
    for (int a = 0; a < 4; a++)
#pragma unroll
        for (int b = 0; b < 4; b++)
#pragma unroll
            for (int r = 0; r < 4; r++) acc[a][b][r] = 0.f;

    uint32_t aoff = (uint32_t)((wm * 64 + (lane & 7) + ((lane >> 3) & 1) * 8) * 80 +
                               (lane >> 4) * 16);
    uint32_t boff = (uint32_t)((wn * 32 + (lane & 7) + (lane >> 4) * 8) * 80 +
                               ((lane >> 3) & 1) * 16);

    int T = KP / 32;
    int TT = KT * T;
    auto issue = [&](int tt) {
        int z = tt / T, kt = (tt % T) * 32;
        uint32_t b = base + (tt & 1) * STG;
        const __nv_bfloat16* aH = d_hH + (size_t)z * NN * 512;
        const __nv_bfloat16* aL = d_hL + (size_t)z * NN * 512;
        const __nv_bfloat16* bH = d_wbH + (size_t)z * 256 * 512;
        const __nv_bfloat16* bL = d_wbL + (size_t)z * 256 * 512;
        cp_plane(aH, b, row0, M, 512, kt, tid);
        cp_plane(aL, b + PL, row0, M, 512, kt, tid);
        cp_plane(bH, b + 2 * PL, col0, 256, 512, kt, tid);
        cp_plane(bL, b + 3 * PL, col0, 256, 512, kt, tid);
        CP_COMMIT();
    };
    issue(0);
    for (int tt = 0; tt < TT; tt++) {
        if (tt + 1 < TT) { issue(tt + 1); CP_WAIT1(); }
        else             { CP_WAIT0(); }
        __syncthreads();
        uint32_t b = base + (tt & 1) * STG;
        mma_slab(b, b + PL, b + 2 * PL, b + 3 * PL, acc, aoff, boff);
        __syncthreads();
    }

#pragma unroll
    for (int mi = 0; mi < 4; mi++)
#pragma unroll
        for (int nj = 0; nj < 4; nj++)
#pragma unroll
            for (int r = 0; r < 4; r++) {
                int row = row0 + wm * 64 + mi * 16 + gid + (r >> 1) * 8;
                int col = col0 + wn * 32 + nj * 8 + 2 * tig + (r & 1);
                if (row < M && col < 256) {
                    float v = acc[mi][nj][r] + bb[col] + bb[256 + col] +
                              bb[512 + col];
                    if (leaky) v = (v > 0.f) ? v : 0.01f * v;
                    dest[(size_t)row * 256 + col] = v;
                }
            }
}

// ---------------- launch ----------------
extern "C" void kernel_launch(void* const* d_in, const int* in_sizes, int n_in,
                              void* d_out, int out_size) {
    float* p_xcur;   // GB300 ATS pitfall: resolve real device address
    cudaGetSymbolAddress((void**)&p_xcur, d_xcur);
    cudaFuncSetAttribute(k_gemm1, cudaFuncAttributeMaxDynamicSharedMemorySize,
                         SMEMSZ);
    cudaFuncSetAttribute(k_gemm2, cudaFuncAttributeMaxDynamicSharedMemorySize,
                         SMEMSZ);

    const float* x = (const float*)d_in[0];
    const int* ei = (const int*)d_in[1];
    const float* ea = (const float*)d_in[2];

    const int ciL[3] = {170, 256, 256};
    const int chL[3] = {340, 512, 512};

    k_count<<<(KT * NE + 255) / 256, 256>>>(ei);
    k_scan<<<KT, 1024>>>();
    k_fill<<<(KT * NE + 255) / 256, 256>>>(ei);

    const float* xin = x;
    for (int l = 0; l < 3; l++) {
        int ci = ciL[l], ch = chL[l];
        int KP1 = (ci + 31) & ~31;
        int KP2 = (ch + 31) & ~31;
        const float* We = (const float*)d_in[3 + l * 8 + 0];
        const float* be = (const float*)d_in[3 + l * 8 + 1];
        const float* Wa = (const float*)d_in[3 + l * 8 + 2];
        const float* ba = (const float*)d_in[3 + l * 8 + 3];
        const float* g  = (const float*)d_in[3 + l * 8 + 4];
        const float* bt = (const float*)d_in[3 + l * 8 + 5];
        const float* Wb = (const float*)d_in[3 + l * 8 + 6];
        const float* bb = (const float*)d_in[3 + l * 8 + 7];
        float* dest = (l == 2) ? (float*)d_out : p_xcur;

        int na = KT * ch * 256;
        k_wsplitA<<<(na + 255) / 256, 256>>>(Wa, ci, ch);
        int nb = KT * 256 * 512;
        k_wsplitB<<<(nb + 255) / 256, 256>>>(Wb, ch);

        k_aggr<<<dim3(NN, KT), 256>>>(xin, ei, ea, We, be, ci);

        dim3 g1((ch + 127) / 128, (NN + 127) / 128, KT);
        k_gemm1<<<g1, 256, SMEMSZ>>>(ba, NN, KP1, ch);

        k_bnfinal<<<KT, 512>>>(g, bt, ch);
        int nh = KT * NN * 128;
        k_hcvt<<<(nh + 255) / 256, 256>>>(ch);

        dim3 g2(2, (NN + 127) / 128);
        k_gemm2<<<g2, 256, SMEMSZ>>>(bb, dest, NN, KP2, (l < 2) ? 1 : 0);

        if (l < 2) xin = p_xcur;
    }
}

// round 17
// speedup vs baseline: 2.0111x; 1.0777x over previous
#include <cuda_runtime.h>
#include <cuda_bf16.h>
#include <cstdint>

#define NN 16500
#define NE 100000
#define KT 3
#define GEN_EPS 1e-7f
#define BN_EPS 1e-5f

// ---------------- scratch ----------------
__device__ int d_cnt[KT][NN];
__device__ int d_off[KT][NN + 1];
__device__ int d_cur[KT][NN];
__device__ int d_eid[KT][NE];
__device__ float d_hh[(size_t)KT * NN * 512];     // GEMM1 out f32, stride=ch
__device__ float d_xcur[NN * 256];
__device__ float d_cs[KT * 512], d_css[KT * 512];
__device__ float d_scale[KT * 512], d_shift[KT * 512];
// planar bf16 hi/lo operands (K zero-padded to fixed strides)
__device__ __nv_bfloat16 d_aggH[(size_t)KT * NN * 256];   // stride 256
__device__ __nv_bfloat16 d_aggL[(size_t)KT * NN * 256];
__device__ __nv_bfloat16 d_hH[(size_t)KT * NN * 512];     // stride 512
__device__ __nv_bfloat16 d_hL[(size_t)KT * NN * 512];
__device__ __nv_bfloat16 d_waH[(size_t)KT * 512 * 256];   // [z][n<=512][k s256]
__device__ __nv_bfloat16 d_waL[(size_t)KT * 512 * 256];
__device__ __nv_bfloat16 d_wbH[(size_t)KT * 256 * 512];   // [z][n<256][k s512]
__device__ __nv_bfloat16 d_wbL[(size_t)KT * 256 * 512];

__device__ __forceinline__ void split_bf16(float v, __nv_bfloat16& hi,
                                           __nv_bfloat16& lo) {
    hi = __float2bfloat16(v);
    lo = __float2bfloat16(v - __bfloat162float(hi));
}
__device__ __forceinline__ uint32_t smem_u32(const void* p) {
    uint32_t a;
    asm("{ .reg .u64 t; cvta.to.shared.u64 t, %1; cvt.u32.u64 %0, t; }"
        : "=r"(a) : "l"(p));
    return a;
}
__device__ __forceinline__ void cpa16(uint32_t dst, const void* src) {
    asm volatile("cp.async.ca.shared.global [%0], [%1], 16;"
                 :: "r"(dst), "l"(src));
}
#define CP_COMMIT() asm volatile("cp.async.commit_group;" ::: "memory")
#define CP_WAIT0()  asm volatile("cp.async.wait_group 0;" ::: "memory")
#define CP_WAIT1()  asm volatile("cp.async.wait_group 1;" ::: "memory")
__device__ __forceinline__ void ldsm4(unsigned r[4], uint32_t a) {
    asm volatile("ldmatrix.sync.aligned.m8n8.x4.shared.b16 {%0,%1,%2,%3}, [%4];"
                 : "=r"(r[0]), "=r"(r[1]), "=r"(r[2]), "=r"(r[3]) : "r"(a));
}
__device__ __forceinline__ void mma_bf16(float* c, const unsigned* a,
                                         const unsigned* b) {
    asm volatile(
        "mma.sync.aligned.m16n8k16.row.col.f32.bf16.bf16.f32 "
        "{%0,%1,%2,%3}, {%4,%5,%6,%7}, {%8,%9}, {%0,%1,%2,%3};"
        : "+f"(c[0]), "+f"(c[1]), "+f"(c[2]), "+f"(c[3])
        : "r"(a[0]), "r"(a[1]), "r"(a[2]), "r"(a[3]), "r"(b[0]), "r"(b[1]));
}

// ---------------- CSR build ----------------
__global__ void k_count(const int* __restrict__ ei) {
    int i = blockIdx.x * blockDim.x + threadIdx.x;
    if (i >= KT * NE) return;
    int k = i / NE, e = i % NE;
    atomicAdd(&d_cnt[k][ei[k * 2 * NE + NE + e]], 1);
}
__global__ void k_scan() {
    __shared__ int sh[1024];
    int k = blockIdx.x, tid = threadIdx.x;
    int carry = 0;
    if (tid == 0) d_off[k][0] = 0;
    for (int base = 0; base < NN; base += 1024) {
        int i = base + tid;
        int v = (i < NN) ? d_cnt[k][i] : 0;
        sh[tid] = v;
        __syncthreads();
        for (int o = 1; o < 1024; o <<= 1) {
            int t = (tid >= o) ? sh[tid - o] : 0;
            __syncthreads();
            sh[tid] += t;
            __syncthreads();
        }
        int inc = sh[tid], tot = sh[1023];
        if (i < NN) {
            d_off[k][i + 1] = carry + inc;
            d_cur[k][i] = carry + inc - v;
        }
        __syncthreads();
        carry += tot;
    }
}
__global__ void k_fill(const int* __restrict__ ei) {
    int i = blockIdx.x * blockDim.x + threadIdx.x;
    if (i < KT * NE) {
        int k = i / NE, e = i % NE;
        int pos = atomicAdd(&d_cur[k][ei[k * 2 * NE + NE + e]], 1);
        d_eid[k][pos] = e;
    }
    if (i < KT * NN) ((int*)d_cnt)[i] = 0;
}

// ---- weight split + transpose to planar [z][n][k-padded] ----
__global__ void k_wsplitA(const float* __restrict__ W, int Kd, int Nd,
                          __nv_bfloat16* __restrict__ oH,
                          __nv_bfloat16* __restrict__ oL) {
    int i = blockIdx.x * blockDim.x + threadIdx.x;
    if (i >= KT * Nd * 256) return;
    int k = i & 255;
    int n = (i >> 8) % Nd;
    int z = i / (Nd * 256);
    float v = (k < Kd) ? W[((size_t)z * Kd + k) * Nd + n] : 0.f;
    __nv_bfloat16 h, l;
    split_bf16(v, h, l);
    size_t o = ((size_t)z * 512 + n) * 256 + k;
    oH[o] = h; oL[o] = l;
}
__global__ void k_wsplitB(const float* __restrict__ W, int Kd,
                          __nv_bfloat16* __restrict__ oH,
                          __nv_bfloat16* __restrict__ oL) {
    int i = blockIdx.x * blockDim.x + threadIdx.x;
    if (i >= KT * 256 * 512) return;
    int k = i & 511;
    int n = (i >> 9) & 255;
    int z = i / (256 * 512);
    float v = (k < Kd) ? W[((size_t)z * Kd + k) * 256 + n] : 0.f;
    __nv_bfloat16 h, l;
    split_bf16(v, h, l);
    oH[i] = h; oL[i] = l;
}

// ---- aggregation: 4 nodes/block, no-max softmax, planar split output ----
#define NB 4
#define ECAP 64
__global__ void k_aggr(const float* __restrict__ xin,
                       const int* __restrict__ ei,
                       const float* __restrict__ ea,
                       const float* __restrict__ WeB,
                       const float* __restrict__ beB, int ci) {
    __shared__ int s_src[NB * ECAP];
    __shared__ float s_a[NB * ECAP];
    __shared__ int s_j0[NB], s_deg[NB];
    int n0 = blockIdx.x * NB, z = blockIdx.y, tid = threadIdx.x;
    if (blockIdx.x == 0) {   // zero BN stats once per type
        for (int i = tid; i < 512; i += 256) {
            d_cs[z * 512 + i] = 0.f;
            d_css[z * 512 + i] = 0.f;
        }
    }
    const int* src = ei + z * 2 * NE;
    const float* eak = ea + z * NE;
    if (tid < NB) {
        int n = n0 + tid;
        int a = (n < NN) ? d_off[z][n] : 0;
        int b = (n < NN) ? d_off[z][n + 1] : 0;
        s_j0[tid] = a;
        s_deg[tid] = b - a;
    }
    __syncthreads();
    {   // one-shot cooperative edge-cache fill: thread -> (node tid>>6, slot tid&63)
        int nb = tid >> 6, j = tid & (ECAP - 1);
        int dg = s_deg[nb];
        if (j < dg && j < ECAP) {
            int e = d_eid[z][s_j0[nb] + j];
            s_src[nb * ECAP + j] = src[e];
            s_a[nb * ECAP + j] = eak[e];
        }
    }
    __syncthreads();

    int c = tid;
    if (c >= ci) return;
    float we = WeB[z * ci + c], bec = beB[z * ci + c];
#pragma unroll
    for (int nb = 0; nb < NB; nb++) {
        int n = n0 + nb;
        if (n >= NN) break;
        int deg = s_deg[nb];
        int cap = min(deg, ECAP);
        float xn = xin[n * ci + c];
        float u0 = fmaxf(xn + we + bec, 0.f) + GEN_EPS;   // self loop (ea=1)
        float den = __expf(u0);
        float ws = u0 * den;
        const int* ss = s_src + nb * ECAP;
        const float* sa = s_a + nb * ECAP;
#pragma unroll 4
        for (int j = 0; j < cap; j++) {
            float u = fmaxf(xin[ss[j] * ci + c] + sa[j] * we + bec, 0.f) + GEN_EPS;
            float e = __expf(u);
            den += e;
            ws = fmaf(u, e, ws);
        }
        for (int jj = cap; jj < deg; jj++) {   // overflow tail (deg>64: ~never)
            int e0 = d_eid[z][s_j0[nb] + jj];
            float u = fmaxf(xin[src[e0] * ci + c] + eak[e0] * we + bec, 0.f) + GEN_EPS;
            float e = __expf(u);
            den += e;
            ws = fmaf(u, e, ws);
        }
        float res = ws / den + xn;
        __nv_bfloat16 h, l;
        split_bf16(res, h, l);
        size_t o = ((size_t)z * NN + n) * 256 + c;
        d_aggH[o] = h;
        d_aggL[o] = l;
    }
}

// ---------------- GEMM machinery (BK=32, stride 80B, ldmatrix) ----------------
#define PL 10240            // one 128x32 bf16 plane (128 rows x 80B)
#define STG (4 * PL)
#define SMEMSZ (2 * STG + 1024)

__device__ __forceinline__ void cp_plane(const __nv_bfloat16* __restrict__ src,
                                         uint32_t dstB, int row0, int rmax,
                                         int stride, int kt, int tid) {
    int q = tid & 3;
    int r = tid >> 2;
#pragma unroll
    for (int it = 0; it < 2; it++) {
        int rr = r + it * 64;
        int rg = row0 + rr;
        if (rg >= rmax) rg = rmax - 1;   // clamp; garbage rows masked later
        const void* s = src + (size_t)rg * stride + kt + q * 8;
        cpa16(dstB + rr * 80 + q * 16, s);
    }
}

__device__ __forceinline__ void mma_slab(uint32_t ahB, uint32_t alB,
                                         uint32_t bhB, uint32_t blB,
                                         float acc[4][4][4], uint32_t aoff,
                                         uint32_t boff) {
#pragma unroll
    for (int ks = 0; ks < 2; ks++) {
        unsigned bh[2][4], bl[2][4];
#pragma unroll
        for (int p = 0; p < 2; p++) {
            uint32_t ba = boff + p * (16 * 80) + ks * 32;
            ldsm4(bh[p], bhB + ba);
            ldsm4(bl[p], blB + ba);
        }
#pragma unroll
        for (int mi = 0; mi < 4; mi++) {
            uint32_t aa = aoff + mi * (16 * 80) + ks * 32;
            unsigned ah[4], al[4];
            ldsm4(ah, ahB + aa);
            ldsm4(al, alB + aa);
#pragma unroll
            for (int p = 0; p < 2; p++) {
                mma_bf16(acc[mi][2 * p], ah, &bh[p][0]);
                mma_bf16(acc[mi][2 * p], ah, &bl[p][0]);
                mma_bf16(acc[mi][2 * p], al, &bh[p][0]);
                mma_bf16(acc[mi][2 * p + 1], ah, &bh[p][2]);
                mma_bf16(acc[mi][2 * p + 1], ah, &bl[p][2]);
                mma_bf16(acc[mi][2 * p + 1], al, &bh[p][2]);
            }
        }
    }
}

// ---- GEMM1: d_hh[z] = agg[z] @ Wa[z] + ba[z]; fused stats; pipelined ----
__global__ __launch_bounds__(256, 2) void k_gemm1(const float* __restrict__ ba,
                                                  int M, int KP, int Nd) {
    extern __shared__ __align__(16) char sm[];
    uint32_t base = smem_u32(sm);
    int tid = threadIdx.x;
    int lane = tid & 31, wid = tid >> 5;
    int wm = wid & 1, wn = wid >> 1;
    int gid = lane >> 2, tig = lane & 3;
    int z = blockIdx.z;
    int row0 = blockIdx.y * 128, col0 = blockIdx.x * 128;

    const __nv_bfloat16* aH = d_aggH + (size_t)z * NN * 256;
    const __nv_bfloat16* aL = d_aggL + (size_t)z * NN * 256;
    const __nv_bfloat16* bH = d_waH + (size_t)z * 512 * 256;
    const __nv_bfloat16* bL = d_waL + (size_t)z * 512 * 256;

    float acc[4][4][4];
#pragma unroll
    for (int a = 0; a < 4; a++)
#pragma unroll
        for (int b = 0; b < 4; b++)
#pragma unroll
            for (int r = 0; r < 4; r++) acc[a][b][r] = 0.f;

    uint32_t aoff = (uint32_t)((wm * 64 + (lane & 7) + ((lane >> 3) & 1) * 8) * 80 +
                               (lane >> 4) * 16);
    uint32_t boff = (uint32_t)((wn * 32 + (lane & 7) + (lane >> 4) * 8) * 80 +
                               ((lane >> 3) & 1) * 16);

    int T = KP / 32;
    auto issue = [&](int t) {
        uint32_t b = base + (t & 1) * STG;
        int kt = t * 32;
        cp_plane(aH, b, row0, M, 256, kt, tid);
        cp_plane(aL, b + PL, row0, M, 256, kt, tid);
        cp_plane(bH, b + 2 * PL, col0, 512, 256, kt, tid);
        cp_plane(bL, b + 3 * PL, col0, 512, 256, kt, tid);
        CP_COMMIT();
    };
    issue(0);
    for (int t = 0; t < T; t++) {
        if (t + 1 < T) { issue(t + 1); CP_WAIT1(); }
        else           { CP_WAIT0(); }
        __syncthreads();
        uint32_t b = base + (t & 1) * STG;
        mma_slab(b, b + PL, b + 2 * PL, b + 3 * PL, acc, aoff, boff);
        __syncthreads();
    }

    float* sS = (float*)(sm + 2 * STG);
    float* sQ = sS + 128;
    if (tid < 128) { sS[tid] = 0.f; sQ[tid] = 0.f; }
    __syncthreads();
    float colS[8], colQ[8];
#pragma unroll
    for (int i = 0; i < 8; i++) { colS[i] = 0.f; colQ[i] = 0.f; }
#pragma unroll
    for (int mi = 0; mi < 4; mi++)
#pragma unroll
        for (int nj = 0; nj < 4; nj++)
#pragma unroll
            for (int r = 0; r < 4; r++) {
                int row = row0 + wm * 64 + mi * 16 + gid + (r >> 1) * 8;
                int col = col0 + wn * 32 + nj * 8 + 2 * tig + (r & 1);
                if (row < M && col < Nd) {
                    float v = acc[mi][nj][r] + ba[z * Nd + col];
                    d_hh[((size_t)z * NN + row) * Nd + col] = v;
                    int i2 = nj * 2 + (r & 1);
                    colS[i2] += v;
                    colQ[i2] += v * v;
                }
            }
#pragma unroll
    for (int i = 0; i < 8; i++) {
        int lc = wn * 32 + (i >> 1) * 8 + 2 * tig + (i & 1);
        atomicAdd(&sS[lc], colS[i]);
        atomicAdd(&sQ[lc], colQ[i]);
    }
    __syncthreads();
    if (tid < 128) {
        int col = col0 + tid;
        if (col < Nd) {
            atomicAdd(&d_cs[z * 512 + col], sS[tid]);
            atomicAdd(&d_css[z * 512 + col], sQ[tid]);
        }
    }
}

// ---- BN finalize + vectorized h convert ----
__global__ void k_bnfinal(const float* __restrict__ gB,
                          const float* __restrict__ btB, int C) {
    int k = blockIdx.x, c = threadIdx.x;
    if (c >= C) return;
    float mu = d_cs[k * 512 + c] / (float)NN;
    float var = d_css[k * 512 + c] / (float)NN - mu * mu;
    var = fmaxf(var, 0.f);
    float s = gB[k * C + c] * rsqrtf(var + BN_EPS);
    d_scale[k * 512 + c] = s;
    d_shift[k * 512 + c] = btB[k * C + c] - mu * s;
}
__global__ void k_hcvt(int ch) {
    int i = blockIdx.x * blockDim.x + threadIdx.x;   // 4 channels / thread
    if (i >= KT * NN * 128) return;
    int c4 = (i & 127) * 4;
    int row = (i >> 7) % NN;
    int z = i / (NN * 128);
    float4 v = make_float4(0.f, 0.f, 0.f, 0.f);
    if (c4 < ch) {
        v = *(const float4*)(d_hh + ((size_t)z * NN + row) * ch + c4);
        const float* sc = d_scale + z * 512 + c4;
        const float* sh = d_shift + z * 512 + c4;
        v.x = fmaxf(fmaf(v.x, sc[0], sh[0]), 0.f);
        v.y = fmaxf(fmaf(v.y, sc[1], sh[1]), 0.f);
        v.z = fmaxf(fmaf(v.z, sc[2], sh[2]), 0.f);
        v.w = fmaxf(fmaf(v.w, sc[3], sh[3]), 0.f);
    }
    __nv_bfloat16 h[4], l[4];
    split_bf16(v.x, h[0], l[0]);
    split_bf16(v.y, h[1], l[1]);
    split_bf16(v.z, h[2], l[2]);
    split_bf16(v.w, h[3], l[3]);
    size_t o = ((size_t)z * NN + row) * 512 + c4;
    *(uint2*)(d_hH + o) = *(const uint2*)h;
    *(uint2*)(d_hL + o) = *(const uint2*)l;
}

// ---- GEMM2: dest = act( sum_z h[z] @ Wb[z] + sum bb ); pipelined over z,t ----
__global__ __launch_bounds__(256, 2) void k_gemm2(const float* __restrict__ bb,
                                                  float* __restrict__ dest,
                                                  int M, int KP, int leaky) {
    extern __shared__ __align__(16) char sm[];
    uint32_t base = smem_u32(sm);
    int tid = threadIdx.x;
    int lane = tid & 31, wid = tid >> 5;
    int wm = wid & 1, wn = wid >> 1;
    int gid = lane >> 2, tig = lane & 3;
    int row0 = blockIdx.y * 128, col0 = blockIdx.x * 128;

    float acc[4][4][4];
#pragma unroll
    for (int a = 0; a < 4; a++)
#pragma unroll
        for (int b = 0; b < 4; b++)
#pragma unroll
            for (int r = 0; r < 4; r++) acc[a][b][r] = 0.f;

    uint32_t aoff = (uint32_t)((wm * 64 + (lane & 7) + ((lane >> 3) & 1) * 8) * 80 +
                               (lane >> 4) * 16);
    uint32_t boff = (uint32_t)((wn * 32 + (lane & 7) + (lane >> 4) * 8) * 80 +
                               ((lane >> 3) & 1) * 16);

    int T = KP / 32;
    int TT = KT * T;
    auto issue = [&](int tt) {
        int z = tt / T, kt = (tt % T) * 32;
        uint32_t b = base + (tt & 1) * STG;
        const __nv_bfloat16* aH = d_hH + (size_t)z * NN * 512;
        const __nv_bfloat16* aL = d_hL + (size_t)z * NN * 512;
        const __nv_bfloat16* bH = d_wbH + (size_t)z * 256 * 512;
        const __nv_bfloat16* bL = d_wbL + (size_t)z * 256 * 512;
        cp_plane(aH, b, row0, M, 512, kt, tid);
        cp_plane(aL, b + PL, row0, M, 512, kt, tid);
        cp_plane(bH, b + 2 * PL, col0, 256, 512, kt, tid);
        cp_plane(bL, b + 3 * PL, col0, 256, 512, kt, tid);
        CP_COMMIT();
    };
    issue(0);
    for (int tt = 0; tt < TT; tt++) {
        if (tt + 1 < TT) { issue(tt + 1); CP_WAIT1(); }
        else             { CP_WAIT0(); }
        __syncthreads();
        uint32_t b = base + (tt & 1) * STG;
        mma_slab(b, b + PL, b + 2 * PL, b + 3 * PL, acc, aoff, boff);
        __syncthreads();
    }

#pragma unroll
    for (int mi = 0; mi < 4; mi++)
#pragma unroll
        for (int nj = 0; nj < 4; nj++)
#pragma unroll
            for (int r = 0; r < 4; r++) {
                int row = row0 + wm * 64 + mi * 16 + gid + (r >> 1) * 8;
                int col = col0 + wn * 32 + nj * 8 + 2 * tig + (r & 1);
                if (row < M && col < 256) {
                    float v = acc[mi][nj][r] + bb[col] + bb[256 + col] +
                              bb[512 + col];
                    if (leaky) v = (v > 0.f) ? v : 0.01f * v;
                    dest[(size_t)row * 256 + col] = v;
                }
            }
}

// ---------------- launch ----------------
extern "C" void kernel_launch(void* const* d_in, const int* in_sizes, int n_in,
                              void* d_out, int out_size) {
    float* p_xcur;   // GB300 ATS pitfall: resolve real device address
    cudaGetSymbolAddress((void**)&p_xcur, d_xcur);
    __nv_bfloat16 *p_waH, *p_waL, *p_wbH, *p_wbL;
    cudaGetSymbolAddress((void**)&p_waH, d_waH);
    cudaGetSymbolAddress((void**)&p_waL, d_waL);
    cudaGetSymbolAddress((void**)&p_wbH, d_wbH);
    cudaGetSymbolAddress((void**)&p_wbL, d_wbL);
    cudaFuncSetAttribute(k_gemm1, cudaFuncAttributeMaxDynamicSharedMemorySize,
                         SMEMSZ);
    cudaFuncSetAttribute(k_gemm2, cudaFuncAttributeMaxDynamicSharedMemorySize,
                         SMEMSZ);

    const float* x = (const float*)d_in[0];
    const int* ei = (const int*)d_in[1];
    const float* ea = (const float*)d_in[2];

    const int ciL[3] = {170, 256, 256};
    const int chL[3] = {340, 512, 512};

    k_count<<<(KT * NE + 255) / 256, 256>>>(ei);
    k_scan<<<KT, 1024>>>();
    k_fill<<<(KT * NE + 255) / 256, 256>>>(ei);

    // Weight splits for ALL layers upfront: independent of the data flow,
    // overlaps with CSR build + early layers. Layer l uses offsets into the
    // shared planar buffers? They'd collide across layers -> give each layer
    // its own region by splitting into the per-layer loop instead. Here:
    // launch layer-0 now, and each layer's splits are re-launched per layer
    // (cheap) but before the aggregation of that layer so they overlap.
    const float* xin = x;
    for (int l = 0; l < 3; l++) {
        int ci = ciL[l], ch = chL[l];
        int KP1 = (ci + 31) & ~31;
        int KP2 = (ch + 31) & ~31;
        const float* We = (const float*)d_in[3 + l * 8 + 0];
        const float* be = (const float*)d_in[3 + l * 8 + 1];
        const float* Wa = (const float*)d_in[3 + l * 8 + 2];
        const float* ba = (const float*)d_in[3 + l * 8 + 3];
        const float* g  = (const float*)d_in[3 + l * 8 + 4];
        const float* bt = (const float*)d_in[3 + l * 8 + 5];
        const float* Wb = (const float*)d_in[3 + l * 8 + 6];
        const float* bb = (const float*)d_in[3 + l * 8 + 7];
        float* dest = (l == 2) ? (float*)d_out : p_xcur;

        int na = KT * ch * 256;
        k_wsplitA<<<(na + 255) / 256, 256>>>(Wa, ci, ch, p_waH, p_waL);
        int nb = KT * 256 * 512;
        k_wsplitB<<<(nb + 255) / 256, 256>>>(Wb, ch, p_wbH, p_wbL);

        k_aggr<<<dim3((NN + NB - 1) / NB, KT), 256>>>(xin, ei, ea, We, be, ci);

        dim3 g1((ch + 127) / 128, (NN + 127) / 128, KT);
        k_gemm1<<<g1, 256, SMEMSZ>>>(ba, NN, KP1, ch);

        k_bnfinal<<<KT, 512>>>(g, bt, ch);
        int nh = KT * NN * 128;
        k_hcvt<<<(nh + 255) / 256, 256>>>(ch);

        dim3 g2(2, (NN + 127) / 128);
        k_gemm2<<<g2, 256, SMEMSZ>>>(bb, dest, NN, KP2, (l < 2) ? 1 : 0);

        if (l < 2) xin = p_xcur;
    }
}